// round 8
// baseline (speedup 1.0000x reference)
#include <cuda_runtime.h>
#include <cstdint>

#define TSTEPS 512
#define BSZ    256
#define DIN    128
#define HID    256
#define NPROTO 128
#define DHTOT  384
#define NB     8            // batches per cluster (2 pipelined groups of 4)
#define CSZ    4            // CTAs per cluster
#define NTHR   512
#define NCTA   128

__device__ float4 g_Wpack[NPROTO][HID];          // [p][h] = {wf, wi, wg, wo}
__device__ float4 g_protoPack[DHTOT/4][NPROTO];  // [q][p] = proto[p][4q..4q+3]
__device__ float  g_pn2[NPROTO];
__device__ unsigned long long g_PP[DIN][NPROTO/2];
__device__ float  g_DOTX[(size_t)TSTEPS*BSZ*NPROTO]; // dot(x,proto_x) - 0.5*||x||^2

typedef unsigned long long u64;

// ---------------- qlstm smem layout (bytes) ----------------
// PROT: [16 q][128 p] float4                 32768   @ 0
// KD  : [2 g][128 p][10 u64]                 20480   @ 32768
// PG  : [8 pc][4 b][2 fi][64 h] u64          32768   @ 53248
// DOT : [2 g][2 buf][4 r][2 pr][128 p] u64   32768   @ 86016
// CN2 : [2 g][2 buf][4 r][2 pr] u64            256   @ 118784
// CMB : [2 g][2 pr][64 h] u64                 2048   @ 119040
#define PROT_OFF 0
#define KD_OFF   32768
#define PG_OFF   53248
#define DOT_OFF  86016
#define CN2_OFF  118784
#define CMB_OFF  119040
#define SMEM_TOTAL 121088

__device__ __forceinline__ u64 pk2(float lo, float hi){
    u64 r; asm("mov.b64 %0, {%1,%2};" : "=l"(r) : "f"(lo), "f"(hi)); return r;
}
__device__ __forceinline__ void upk2(u64 v, float& lo, float& hi){
    asm("mov.b64 {%0,%1}, %2;" : "=f"(lo), "=f"(hi) : "l"(v));
}
__device__ __forceinline__ u64 ffma2(u64 a, u64 b, u64 c){
    u64 d; asm("fma.rn.f32x2 %0, %1, %2, %3;" : "=l"(d) : "l"(a), "l"(b), "l"(c)); return d;
}
__device__ __forceinline__ u64 add2(u64 a, u64 b){
    u64 d; asm("add.rn.f32x2 %0, %1, %2;" : "=l"(d) : "l"(a), "l"(b)); return d;
}
__device__ __forceinline__ float sigmf(float x){
    return __fdividef(1.f, 1.f + __expf(-x));
}
__device__ __forceinline__ float tanhf_(float x){
    return 1.f - __fdividef(2.f, __expf(2.f*x) + 1.f);
}
__device__ __forceinline__ uint32_t smem_u32(const void* p){
    uint32_t a;
    asm("{ .reg .u64 t; cvta.to.shared.u64 t, %1; cvt.u32.u64 %0, t; }" : "=r"(a) : "l"(p));
    return a;
}
__device__ __forceinline__ uint32_t ctarank(){
    uint32_t r; asm("mov.u32 %0, %%cluster_ctarank;" : "=r"(r)); return r;
}
__device__ __forceinline__ uint32_t mapa_u32(uint32_t local, uint32_t rank){
    uint32_t r; asm("mapa.shared::cluster.u32 %0, %1, %2;" : "=r"(r) : "r"(local), "r"(rank));
    return r;
}
__device__ __forceinline__ void st_cl64(uint32_t addr, u64 v){
    asm volatile("st.shared::cluster.b64 [%0], %1;" :: "r"(addr), "l"(v) : "memory");
}
__device__ __forceinline__ void cl_arrive(){
    asm volatile("barrier.cluster.arrive.aligned;" ::: "memory");
}
__device__ __forceinline__ void cl_wait(){
    asm volatile("barrier.cluster.wait.aligned;"   ::: "memory");
}
__device__ __forceinline__ u64 shfl_xor64(u64 v, int off){
    uint32_t lo = (uint32_t)v, hi = (uint32_t)(v >> 32);
    lo = __shfl_xor_sync(0xffffffffu, lo, off);
    hi = __shfl_xor_sync(0xffffffffu, hi, off);
    return ((u64)hi << 32) | lo;
}

// ============ pack ============
__global__ void pack_kernel(const float* __restrict__ proto,
                            const float* __restrict__ Wf, const float* __restrict__ Wi,
                            const float* __restrict__ Wg, const float* __restrict__ Wo){
    int idx = blockIdx.x * blockDim.x + threadIdx.x;
    if (idx < HID*NPROTO){
        int h = idx >> 7, pp = idx & (NPROTO-1);
        g_Wpack[pp][h] = make_float4(Wf[idx], Wi[idx], Wg[idx], Wo[idx]);
    }
    if (idx < (DHTOT/4)*NPROTO){
        int q = idx >> 7, pp = idx & (NPROTO-1);
        const float* pr = proto + pp*DHTOT + 4*q;
        g_protoPack[q][pp] = make_float4(pr[0], pr[1], pr[2], pr[3]);
    }
    if (idx < DIN*(NPROTO/2)){
        int d = idx >> 6, pp = idx & 63;
        g_PP[d][pp] = pk2(proto[(2*pp)*DHTOT + d], proto[(2*pp+1)*DHTOT + d]);
    }
    if (idx < NPROTO){
        float s = 0.f;
        for (int d = 0; d < DHTOT; ++d){ float v = proto[idx*DHTOT + d]; s = fmaf(v, v, s); }
        g_pn2[idx] = s;
    }
}

// ============ DOTX precompute ============
extern __shared__ char psm[];
__global__ __launch_bounds__(512, 1)
void dotx_kernel(const float* __restrict__ x){
    u64* PPs = reinterpret_cast<u64*>(psm);        // [128 d][64 pp]
    const int tid = threadIdx.x;
    const int lane = tid & 31, wrp = tid >> 5;
    #pragma unroll
    for (int i = 0; i < 16; ++i)
        PPs[tid + i*512] = ((const u64*)g_PP)[tid + i*512];
    __syncthreads();

    const int pg = lane & 7;
    const int rp = (wrp << 2) | (lane >> 3);
    const size_t r0 = (size_t)blockIdx.x*128 + rp*2;
    const float4* xr0 = reinterpret_cast<const float4*>(x + r0*DIN);
    const float4* xr1 = reinterpret_cast<const float4*>(x + (r0+1)*DIN);

    u64 accA[8], accB[8];
    #pragma unroll
    for (int i = 0; i < 8; ++i){ accA[i] = 0ull; accB[i] = 0ull; }
    float n0 = 0.f, n1 = 0.f;

    #pragma unroll 4
    for (int dq = 0; dq < 32; ++dq){
        float4 fa = __ldcg(&xr0[dq]);
        float4 fb = __ldcg(&xr1[dq]);
        const float a[4] = {fa.x, fa.y, fa.z, fa.w};
        const float b[4] = {fb.x, fb.y, fb.z, fb.w};
        #pragma unroll
        for (int l = 0; l < 4; ++l){
            int d = dq*4 + l;
            u64 va = pk2(a[l], a[l]);
            u64 vb = pk2(b[l], b[l]);
            n0 = fmaf(a[l], a[l], n0);
            n1 = fmaf(b[l], b[l], n1);
            const u64* row = PPs + d*64 + pg;
            #pragma unroll
            for (int i = 0; i < 8; ++i){
                u64 pv = row[i*8];
                accA[i] = ffma2(va, pv, accA[i]);
                accB[i] = ffma2(vb, pv, accB[i]);
            }
        }
    }
    u64 nA2 = pk2(-0.5f*n0, -0.5f*n0);
    u64 nB2 = pk2(-0.5f*n1, -0.5f*n1);
    u64* DX = reinterpret_cast<u64*>(g_DOTX);
    #pragma unroll
    for (int i = 0; i < 8; ++i){
        int pp = i*8 + pg;
        DX[r0*64 + pp]     = add2(accA[i], nA2);
        DX[(r0+1)*64 + pp] = add2(accB[i], nB2);
    }
}

// ============ recurrent kernel: two pipelined groups ============
extern __shared__ char sm[];

__global__ void __cluster_dims__(CSZ,1,1) __launch_bounds__(NTHR, 1)
qlstm_kernel(const float* __restrict__ bf, const float* __restrict__ bi,
             const float* __restrict__ bg, const float* __restrict__ bo,
             float* __restrict__ out){
    const int tid  = threadIdx.x;
    const int lane = tid & 31;
    const int wrp  = tid >> 5;
    const uint32_t rank = ctarank();
    const int bbase = (blockIdx.x >> 2) * NB;
    const uint32_t base = smem_u32(sm);

    float4* PROT = reinterpret_cast<float4*>(sm + PROT_OFF);
    u64*    KDu  = reinterpret_cast<u64*>(sm + KD_OFF);
    u64*    PGu  = reinterpret_cast<u64*>(sm + PG_OFF);
    u64*    DOTu = reinterpret_cast<u64*>(sm + DOT_OFF);
    u64*    CN2u = reinterpret_cast<u64*>(sm + CN2_OFF);
    u64*    CMBu = reinterpret_cast<u64*>(sm + CMB_OFF);   // [2 g][2 pr][64 h]
    float*  CMBF = reinterpret_cast<float*>(sm + CMB_OFF);

    // roles
    const int hhD = lane & 1;                       // dist h-half
    const int pDd = ((wrp & 7) << 4) + (lane >> 1); // dist p
    const int prD = wrp >> 3;                       // dist pair (0..1)
    const int pK  = tid & 127;                      // K p (tid<256)
    const int prK = (tid >> 7) & 1;                 // K pair
    const int hL  = tid & 63;                       // gate/reduce h_local
    const int pcG = tid >> 6;                       // gate p-chunk 0..7
    const int bRr = tid >> 6;                       // reduce batch 0..3 (tid<256)
    const int hglob = (int)rank*64 + hL;

    // ---------- preamble ----------
    #pragma unroll
    for (int i = 0; i < 4; ++i){
        int idx = tid + i*NTHR;
        int q = idx >> 7, p = idx & 127;
        PROT[q*128 + p] = g_protoPack[32 + (int)rank*16 + q][p];
    }
    u64 wFI[16], wGO[16];
    #pragma unroll
    for (int j = 0; j < 16; ++j){
        float4 w = g_Wpack[pcG*16 + j][hglob];
        wFI[j] = pk2(w.x, w.y);
        wGO[j] = pk2(w.z, w.w);
    }
    if (tid < 256) CMBu[tid] = 0ull;                // zero hv, both groups (256 u64 total)

    const u64 bFI = pk2(bf[hglob], bi[hglob]);
    const u64 bGO = pk2(bg[hglob], bo[hglob]);
    const float pn2v = g_pn2[pK];

    // DSMEM addresses (group/buf offsets added at use)
    uint32_t dotA[CSZ], cnA[CSZ];
    {
        uint32_t dOff = base + DOT_OFF + rank*2048u + (uint32_t)(prD*1024 + pDd*8);
        uint32_t cOff = base + CN2_OFF + rank*16u + (uint32_t)(wrp*8);   // cn2 role (tid<64)
        #pragma unroll
        for (uint32_t r = 0; r < CSZ; ++r){
            dotA[r] = mapa_u32(dOff, r);
            cnA[r]  = mapa_u32(cOff, r);
        }
    }

    float cxA = 0.f, cxB = 0.f, hvA = 0.f, hvB = 0.f;

    __syncthreads();
    cl_arrive(); cl_wait();

    for (int i = 0; i <= 2*TSTEPS; ++i){
        const int gd = i & 1;          // dist group this half
        const int td = i >> 1;         // dist time
        const int gk = gd ^ 1;         // gate/K group this half
        const int tk = (i - 1) >> 1;   // gate/K time

        // DOTX prefetch for K_{gk}(tk)
        float dx0 = 0.f, dx1 = 0.f;
        if (i > 0 && tid < 256){
            const float* dxp = g_DOTX +
                ((size_t)tk*BSZ + bbase + gk*4 + 2*prK)*NPROTO + pK;
            dx0 = __ldcg(dxp);
            dx1 = __ldcg(dxp + NPROTO);
        }

        __syncthreads();               // S1: hv(gd) + prior-phase smem settled

        if (i < 2*TSTEPS){
            // ---- dist_gd(td): thread=(pDd, hhD, prD), 32 h each ----
            u64 aA = 0ull, aB = 0ull;
            const float4* pp = PROT + (hhD*8)*128 + pDd;
            const ulonglong2* cb = reinterpret_cast<const ulonglong2*>(
                CMBu + gd*128 + prD*64 + hhD*32);
            #pragma unroll
            for (int j = 0; j < 8; ++j){
                float4 pv = pp[j*128];
                ulonglong2 cA = cb[j*2];
                ulonglong2 cB = cb[j*2 + 1];
                aA = ffma2(cA.x, pk2(pv.x, pv.x), aA);
                aB = ffma2(cA.y, pk2(pv.y, pv.y), aB);
                aA = ffma2(cB.x, pk2(pv.z, pv.z), aA);
                aB = ffma2(cB.y, pk2(pv.w, pv.w), aB);
            }
            u64 a = add2(aA, aB);
            a = add2(a, shfl_xor64(a, 1));          // combine h-halves
            if (hhD == 0){
                uint32_t off = (uint32_t)(gd*16384 + (td & 1)*8192);
                #pragma unroll
                for (int r = 0; r < CSZ; ++r) st_cl64(dotA[r] + off, a);
            }
            // ---- cn2_gd: warps 0-1 (pr = wrp) ----
            if (tid < 64){
                const u64* cb2 = CMBu + gd*128 + wrp*64;
                u64 c0 = cb2[lane], c1 = cb2[lane + 32];
                u64 s = ffma2(c0, c0, ffma2(c1, c1, 0ull));
                #pragma unroll
                for (int off2 = 16; off2; off2 >>= 1)
                    s = add2(s, shfl_xor64(s, off2));
                if (lane == 0){
                    uint32_t off = (uint32_t)(gd*128 + (td & 1)*64);
                    #pragma unroll
                    for (int r = 0; r < CSZ; ++r) st_cl64(cnA[r] + off, s);
                }
            }
        }

        cl_arrive();                   // release dist_gd partials

        if (i > 0){
            // ---- K_gk(tk): tid<256, partials acquired by wait(i-1) ----
            if (tid < 256){
                const int bufk = tk & 1;
                const u64* db = DOTu + gk*2048 + bufk*1024 + prK*128 + pK;
                u64 ds = add2(add2(db[0], db[256]), add2(db[512], db[768]));
                const u64* cn = CN2u + gk*16 + bufk*8 + prK;
                u64 cs = add2(add2(cn[0], cn[2]), add2(cn[4], cn[6]));
                float d0, d1, c0, c1;
                upk2(ds, d0, d1); upk2(cs, c0, c1);
                float k0 = __expf(2.f*(d0 + dx0) - pn2v - c0);
                float k1 = __expf(2.f*(d1 + dx1) - pn2v - c1);
                ulonglong2 kk; kk.x = pk2(k0, k0); kk.y = pk2(k1, k1);
                *reinterpret_cast<ulonglong2*>(KDu + gk*1280 + pK*10 + prK*2) = kk;
            }
            __syncthreads();           // S2: KD_gk ready

            // ---- gate_gk: thread=(hL, pcG), 16 p, 4 batches ----
            {
                u64 F0=0,F1=0,F2=0,F3=0,G0=0,G1=0,G2=0,G3=0;
                const ulonglong2* kp =
                    reinterpret_cast<const ulonglong2*>(KDu + gk*1280) + (pcG*16)*5;
                #pragma unroll 4
                for (int j = 0; j < 16; ++j){
                    ulonglong2 kA = kp[j*5 + 0];
                    ulonglong2 kB = kp[j*5 + 1];
                    F0 = ffma2(wFI[j], kA.x, F0);  G0 = ffma2(wGO[j], kA.x, G0);
                    F1 = ffma2(wFI[j], kA.y, F1);  G1 = ffma2(wGO[j], kA.y, G1);
                    F2 = ffma2(wFI[j], kB.x, F2);  G2 = ffma2(wGO[j], kB.x, G2);
                    F3 = ffma2(wFI[j], kB.y, F3);  G3 = ffma2(wGO[j], kB.y, G3);
                }
                u64* pg = PGu + hL;    // [pc][b][fi][64]
                pg[((pcG*4 + 0)*2 + 0)*64] = F0;  pg[((pcG*4 + 0)*2 + 1)*64] = G0;
                pg[((pcG*4 + 1)*2 + 0)*64] = F1;  pg[((pcG*4 + 1)*2 + 1)*64] = G1;
                pg[((pcG*4 + 2)*2 + 0)*64] = F2;  pg[((pcG*4 + 2)*2 + 1)*64] = G2;
                pg[((pcG*4 + 3)*2 + 0)*64] = F3;  pg[((pcG*4 + 3)*2 + 1)*64] = G3;
            }
            __syncthreads();           // S3: PG ready

            // ---- reduce + activations: tid<256, thread=(hL, bRr) ----
            if (tid < 256){
                u64 Fa = bFI, Ga = bGO;
                #pragma unroll
                for (int c = 0; c < 8; ++c){
                    Fa = add2(Fa, PGu[((c*4 + bRr)*2 + 0)*64 + hL]);
                    Ga = add2(Ga, PGu[((c*4 + bRr)*2 + 1)*64 + hL]);
                }
                float fp, ip, gp, op;
                upk2(Fa, fp, ip); upk2(Ga, gp, op);
                float fv = sigmf(fp), iv = sigmf(ip), gv = tanhf_(gp), ov = sigmf(op);
                float cxv = gk ? cxB : cxA;
                cxv = fv*cxv + iv*gv;
                float hvv = ov * tanhf_(cxv);
                if (gk){ cxB = cxv; hvB = hvv; } else { cxA = cxv; hvA = hvv; }
                CMBF[(gk*128 + (bRr >> 1)*64 + hL)*2 + (bRr & 1)] = hvv;
                out[((size_t)tk*BSZ + bbase + gk*4 + bRr)*HID + hglob] = hvv;
            }
        }

        cl_wait();                     // acquire dist partials from all ranks
    }

    // ---- finals ----
    if (tid < 256){
        const size_t TBH = (size_t)TSTEPS * BSZ * HID;
        const size_t BH  = (size_t)BSZ * HID;
        out[TBH + (size_t)(bbase + bRr)*HID + hglob]          = hvA;
        out[TBH + (size_t)(bbase + 4 + bRr)*HID + hglob]      = hvB;
        out[TBH + BH + (size_t)(bbase + bRr)*HID + hglob]     = cxA;
        out[TBH + BH + (size_t)(bbase + 4 + bRr)*HID + hglob] = cxB;
    }
}

extern "C" void kernel_launch(void* const* d_in, const int* in_sizes, int n_in,
                              void* d_out, int out_size){
    (void)in_sizes; (void)n_in; (void)out_size;
    const float* inputs = (const float*)d_in[0];
    const float* proto  = (const float*)d_in[1];
    const float* Wf     = (const float*)d_in[2];
    const float* bf     = (const float*)d_in[3];
    const float* Wi     = (const float*)d_in[4];
    const float* bi     = (const float*)d_in[5];
    const float* Wg     = (const float*)d_in[6];
    const float* bg     = (const float*)d_in[7];
    const float* Wo     = (const float*)d_in[8];
    const float* bo     = (const float*)d_in[9];
    float* out = (float*)d_out;

    cudaFuncSetAttribute(qlstm_kernel,
                         cudaFuncAttributeMaxDynamicSharedMemorySize, SMEM_TOTAL);
    cudaFuncSetAttribute(dotx_kernel,
                         cudaFuncAttributeMaxDynamicSharedMemorySize, 65536);

    pack_kernel<<<(HID*NPROTO + 511)/512, 512>>>(proto, Wf, Wi, Wg, Wo);
    dotx_kernel<<<(TSTEPS*BSZ)/128, 512, 65536>>>(inputs);
    qlstm_kernel<<<NCTA, NTHR, SMEM_TOTAL>>>(bf, bi, bg, bo, out);
}